// round 17
// baseline (speedup 1.0000x reference)
#include <cuda_runtime.h>
#include <cuda_fp16.h>

#define BS   8
#define CH   256
#define TLEN 512
#define PBIN 16
#define SRAT 4

// 2 MB transposed-input scratch in FP16 (b, t, c) + one zero pad row so the
// unconditional hi = lo + 512B load is safe at xl = 511 of the last batch
// (whi = 0 there, and device globals are zero-initialized).
__device__ __half2 g_tr[BS * TLEN * CH / 2 + CH / 2];

// ---------------------------------------------------------------------------
// Kernel 1: transpose (b, ch, t) fp32 -> (b, t, ch) fp16. 32x32 tiles.
// ---------------------------------------------------------------------------
__global__ __launch_bounds__(256) void transpose_kernel(const float* __restrict__ in) {
    __shared__ float tile[32][33];
    const int b  = blockIdx.z;
    const int t0 = blockIdx.x * 32;
    const int c0 = blockIdx.y * 32;
    const int tx = threadIdx.x;          // 0..7  (float4 index)
    const int ty = threadIdx.y;          // 0..31

    const float* inb  = in   + (size_t)b * CH * TLEN;
    __half2*     outb = g_tr + (size_t)b * TLEN * (CH / 2);

    const float4 v = *(const float4*)&inb[(size_t)(c0 + ty) * TLEN + (t0 + 4 * tx)];
    tile[ty][4 * tx + 0] = v.x;
    tile[ty][4 * tx + 1] = v.y;
    tile[ty][4 * tx + 2] = v.z;
    tile[ty][4 * tx + 3] = v.w;
    __syncthreads();

    __half2 w2[2];
    w2[0] = __floats2half2_rn(tile[4 * tx + 0][ty], tile[4 * tx + 1][ty]);
    w2[1] = __floats2half2_rn(tile[4 * tx + 2][ty], tile[4 * tx + 3][ty]);
    *(uint2*)&outb[(size_t)(t0 + ty) * (CH / 2) + (c0 / 2 + 2 * tx)] = *(const uint2*)w2;
}

// ---------------------------------------------------------------------------
// Kernel 2: fp16 gathers + HFMA2, uint2 descriptors, UNROLL-8 bins.
//   TWO 64-thread blocks per ROI (128 channels each). Thread owns channel
//   pair (2l, 2l+1); one address per sample (hi row = +512B immediate).
//   Up to 64 one-line LDGs in flight per thread (probing the per-warp
//   outstanding-LDG cap); __launch_bounds__(64,16) -> <=64 regs, 32 warps/SM.
//   half2 staging (STS.32 conflict-free); fp32 convert in the writeback.
// ---------------------------------------------------------------------------
#define S2H 132   // half2 stage row stride (channel pairs + skew)

__device__ __forceinline__ unsigned h2u(__half2 h) {
    return *reinterpret_cast<unsigned*>(&h);
}
__device__ __forceinline__ __half2 u2h(unsigned u) {
    return *reinterpret_cast<__half2*>(&u);
}

__global__ __launch_bounds__(64, 16) void roialign_kernel(const float* __restrict__ rois,
                                                          float4* __restrict__ out) {
    const int half = blockIdx.x & 1;         // which 128-channel half
    const int n    = blockIdx.x >> 1;        // ROI index
    const int l    = threadIdx.x;            // 0..63

    __shared__ uint2   s_desc[PBIN * SRAT];  // (row-offset, packed (wlo,whi))
    __shared__ __half2 s_stage[PBIN * S2H];  // [p][64 chan-pairs] skewed rows

    // ---- Phase A: per-sample descriptors (thread i == sample i) ----
    {
        const float bf    = __ldg(&rois[n * 3 + 0]);
        const float start = __ldg(&rois[n * 3 + 1]);
        const float end   = __ldg(&rois[n * 3 + 2]);
        const float roi_len = fmaxf(end - start, 1.0f);
        const float bin     = roi_len * (1.0f / (float)PBIN);

        const int p = l >> 2;                // bin
        const int s = l & 3;                 // sample
        const float x = start + ((float)p + ((float)s + 0.5f) * 0.25f) * bin;
        const bool valid = (x >= -1.0f) && (x <= (float)TLEN);
        const float xc = fminf(fmaxf(x, 0.0f), (float)(TLEN - 1));
        const int xl = (int)floorf(xc);
        const float lx = xc - (float)xl;     // lx = 0 when xl = 511 -> whi = 0
        const int b = (int)bf;

        const float wlo = valid ? (1.0f - lx) * 0.25f : 0.0f;
        const float whi = valid ? lx * 0.25f : 0.0f;

        uint2 d;
        d.x = (unsigned)(((b << 9) + xl) << 9);        // byte offset of row xl
        d.y = h2u(__floats2half2_rn(wlo, whi));        // packed weights
        s_desc[l] = d;
    }
    __syncthreads();

    // ---- Phase B: one-line fp16 gathers, 8 bins per iteration ----
    const char* base = (const char*)g_tr + (half * 128 + 2 * l) * 2;

    #pragma unroll 8
    for (int p = 0; p < PBIN; p++) {
        __half2 acc = __float2half2_rn(0.0f);
        #pragma unroll
        for (int s = 0; s < SRAT; s++) {
            const uint2 d = s_desc[p * SRAT + s];
            const char* a = base + d.x;
            const __half2 lo = *(const __half2*)(a);
            const __half2 hi = *(const __half2*)(a + 512);
            const __half2 w  = u2h(d.y);
            acc = __hfma2(lo, __low2half2(w), acc);
            acc = __hfma2(hi, __high2half2(w), acc);
        }
        // STS.32: 64 threads x 4B span 256B; conflict-free per half-warp.
        s_stage[p * S2H + l] = acc;
    }
    __syncthreads();

    // ---- Phase C: coalesced float4 writeback (contiguous half-ROI range) ----
    float4* outn = out + (size_t)n * (CH * PBIN / 4) + half * 512;

    #pragma unroll
    for (int k = 0; k < 8; k++) {
        const int q = l + 64 * k;            // 0..511, coalesced
        const int cp = q >> 3;               // channel pair (0..63)
        const int g  = q & 3;                // bin-group
        const int hl = (q >> 2) & 1;         // low/high half of the pair
        float4 v;
        #pragma unroll
        for (int j = 0; j < 4; j++) {
            const float2 f2 = __half22float2(s_stage[(4 * g + j) * S2H + cp]);
            ((float*)&v)[j] = hl ? f2.y : f2.x;
        }
        // out element index: c*16 + p with c = 2cp + hl, p = 4g + j
        outn[(2 * cp + hl) * 4 + g] = v;
    }
}

extern "C" void kernel_launch(void* const* d_in, const int* in_sizes, int n_in,
                              void* d_out, int out_size) {
    const float* input = (const float*)d_in[0];
    const float* rois  = (const float*)d_in[1];
    float4*      out   = (float4*)d_out;

    const int N = in_sizes[1] / 3;       // 2048 ROIs

    dim3 tgrid(TLEN / 32, CH / 32, BS);  // (16, 8, 8)
    dim3 tblk(8, 32);
    transpose_kernel<<<tgrid, tblk>>>(input);

    roialign_kernel<<<N * 2, 64>>>(rois, out);
}